// round 6
// baseline (speedup 1.0000x reference)
#include <cuda_runtime.h>
#include <cuda_fp16.h>
#include <math_constants.h>

typedef unsigned int u32;

// Problem: inputs [64,32,32,64] f32 -> N=65536 rows, D=64; embeddings [64,512] f32.
// Output (f32 concat): quantized [N*64] | indices [N] | loss [1]
#define N_ROWS   65536
#define DIM      64
#define KCODES   512
#define ROWS_BLK 128
#define CHUNK    64
#define NCHUNKS  (KCODES / CHUNK)        // 8
#define THREADS  256
#define NBLOCKS  (N_ROWS / ROWS_BLK)     // 512

#define Q_ELEMS  ((size_t)N_ROWS * DIM)
#define IDX_OFF  Q_ELEMS
#define LOSS_OFF (Q_ELEMS + N_ROWS)

// SMEM layout (bytes)
#define ASTRIDE   144                    // 128B fp16 row + 16B pad
#define BSTRIDE   144                    // 64 codes x 2B + 16B pad
#define OFF_A     0                      // 128 x 144 = 18432
#define OFF_B     (OFF_A + ROWS_BLK * ASTRIDE)        // 18432
#define OFF_ENORM (OFF_B + DIM * BSTRIDE)             // 27648
#define OFF_ROWCODE (OFF_ENORM + KCODES * 4)          // 29696
#define OFF_FLAGC (OFF_ROWCODE + ROWS_BLK * 4)        // 30208
#define OFF_FLAGL (OFF_FLAGC + 16)                    // 30224
#define SMEM_TOTAL (OFF_FLAGL + ROWS_BLK * 4 + 16)    // ~30756

// fp16 error band: dist err <= 2*2^-10*||x||*||e|| <= ~3e-2; flip band ~6e-2.
#define BAND_T 0.09f

__device__ float g_partials[NBLOCKS];
__device__ int   g_done = 0;

// ---------------------------------------------------------------------------
static __device__ __forceinline__ u32 smem_u32(const void* p) {
    u32 a;
    asm("{ .reg .u64 t; cvta.to.shared.u64 t, %1; cvt.u32.u64 %0, t; }" : "=r"(a) : "l"(p));
    return a;
}
static __device__ __forceinline__ void ldsm_x4(u32& r0, u32& r1, u32& r2, u32& r3, u32 a) {
    asm volatile("ldmatrix.sync.aligned.m8n8.x4.shared.b16 {%0,%1,%2,%3}, [%4];"
                 : "=r"(r0), "=r"(r1), "=r"(r2), "=r"(r3) : "r"(a));
}
static __device__ __forceinline__ void ldsm_x2t(u32& r0, u32& r1, u32 a) {
    asm volatile("ldmatrix.sync.aligned.m8n8.x2.trans.shared.b16 {%0,%1}, [%2];"
                 : "=r"(r0), "=r"(r1) : "r"(a));
}
static __device__ __forceinline__ void mma_f16(float* c, u32 a0, u32 a1, u32 a2, u32 a3,
                                               u32 b0, u32 b1) {
    asm volatile("mma.sync.aligned.m16n8k16.row.col.f32.f16.f16.f32 "
                 "{%0,%1,%2,%3}, {%4,%5,%6,%7}, {%8,%9}, {%0,%1,%2,%3};"
                 : "+f"(c[0]), "+f"(c[1]), "+f"(c[2]), "+f"(c[3])
                 : "r"(a0), "r"(a1), "r"(a2), "r"(a3), "r"(b0), "r"(b1));
}

// ---------------------------------------------------------------------------
// Single fused kernel
// ---------------------------------------------------------------------------
__global__ void __launch_bounds__(THREADS, 2)
vq_kernel(const float* __restrict__ X, const float* __restrict__ E,
          float* __restrict__ out, int out_size) {
    extern __shared__ char smem[];
    const u32 sb   = smem_u32(smem);
    const int tid  = threadIdx.x;
    const int lane = tid & 31;
    const int warp = tid >> 5;
    const int rowBase = blockIdx.x * ROWS_BLK;
    const int warpRow = warp * 16;

    float* enorm_s  = reinterpret_cast<float*>(smem + OFF_ENORM);
    int*   rowcode  = reinterpret_cast<int*>(smem + OFF_ROWCODE);
    int*   flagcnt  = reinterpret_cast<int*>(smem + OFF_FLAGC);
    int*   flaglist = reinterpret_cast<int*>(smem + OFF_FLAGL);

    if (tid == 0) *flagcnt = 0;

    // ---- A tile: fp32 -> fp16, [row][d] stride 144 ----
    #pragma unroll
    for (int it = 0; it < 4; ++it) {
        int task = tid + THREADS * it;            // 1024 tasks: 128 rows x 8 groups
        int r  = task >> 3;
        int d0 = (task & 7) * 8;
        const float4* xv = reinterpret_cast<const float4*>(
            X + (size_t)(rowBase + r) * DIM + d0);
        float4 v0 = xv[0], v1 = xv[1];
        float vals[8] = {v0.x, v0.y, v0.z, v0.w, v1.x, v1.y, v1.z, v1.w};
        union { __half h[8]; uint4 u; } ph;
        #pragma unroll
        for (int e = 0; e < 8; ++e) ph.h[e] = __float2half_rn(vals[e]);
        *reinterpret_cast<uint4*>(smem + OFF_A + r * ASTRIDE + d0 * 2) = ph.u;
    }

    // ---- enorm per CTA (coalesced across lanes) ----
    #pragma unroll
    for (int it = 0; it < 2; ++it) {
        int k = tid + THREADS * it;
        float s = 0.f;
        #pragma unroll 16
        for (int d = 0; d < DIM; ++d) {
            float e = E[(size_t)d * KCODES + k];
            s = fmaf(e, e, s);
        }
        enorm_s[k] = s;
    }

    // ldmatrix base addresses
    const int mA = lane >> 3, rA8 = lane & 7;
    const u32 aBase = sb + OFF_A + (u32)((warpRow + (mA & 1) * 8 + rA8) * ASTRIDE
                                         + (mA >> 1) * 16);
    const u32 bBase = sb + OFF_B + (u32)((lane & 15) * BSTRIDE);   // d-row per lane

    // top-2 values + top-1 index, two rows per thread
    float b1a = CUDART_INF_F, b2a = CUDART_INF_F;
    float b1b = CUDART_INF_F, b2b = CUDART_INF_F;
    int   i1a = 0, i1b = 0;

    for (int ch = 0; ch < NCHUNKS; ++ch) {
        const int c0 = ch * CHUNK;
        __syncthreads();          // previous chunk's B reads complete (and A stores on ch0)
        // stage B chunk: convert E[d][c0..c0+63] fp32 -> fp16 [d][c] stride 144
        #pragma unroll
        for (int it = 0; it < 8; ++it) {
            int i  = tid + THREADS * it;          // 2048 tasks: 64 d x 32 pairs
            int d  = i >> 5;
            int c2 = (i & 31) * 2;
            float2 v = *reinterpret_cast<const float2*>(E + (size_t)d * KCODES + c0 + c2);
            __half2 h = __floats2half2_rn(v.x, v.y);
            *reinterpret_cast<__half2*>(smem + OFF_B + d * BSTRIDE + c2 * 2) = h;
        }
        __syncthreads();

        float acc[8][4];
        #pragma unroll
        for (int nt = 0; nt < 8; ++nt)
            #pragma unroll
            for (int j = 0; j < 4; ++j) acc[nt][j] = 0.f;

        #pragma unroll
        for (int ks = 0; ks < 4; ++ks) {
            u32 a0, a1, a2, a3;
            ldsm_x4(a0, a1, a2, a3, aBase + ks * 32);
            #pragma unroll
            for (int nt = 0; nt < 8; ++nt) {
                u32 b0, b1;
                ldsm_x2t(b0, b1, bBase + (u32)(ks * 16 * BSTRIDE) + nt * 16);
                mma_f16(acc[nt], a0, a1, a2, a3, b0, b1);
            }
        }

        // running top-2 argmin (codes ascend -> lowest index wins ties)
        const int colBase = 2 * (lane & 3);
        #pragma unroll
        for (int nt = 0; nt < 8; ++nt) {
            int   code0 = c0 + nt * 8 + colBase;
            float e0 = enorm_s[code0], e1 = enorm_s[code0 + 1];
            float v;
            #define UPD(B1, I1, B2, VAL, IDX)                        \
                do { v = (VAL);                                      \
                     bool p = v < B1;                                \
                     B2 = fminf(B2, fmaxf(v, B1));                   \
                     B1 = fminf(B1, v);                              \
                     I1 = p ? (IDX) : I1; } while (0)
            UPD(b1a, i1a, b2a, fmaf(-2.f, acc[nt][0], e0), code0);
            UPD(b1a, i1a, b2a, fmaf(-2.f, acc[nt][1], e1), code0 + 1);
            UPD(b1b, i1b, b2b, fmaf(-2.f, acc[nt][2], e0), code0);
            UPD(b1b, i1b, b2b, fmaf(-2.f, acc[nt][3], e1), code0 + 1);
            #undef UPD
        }
    }

    // ---- cross-lane merge within quad (top-2 values + top-1 index) ----
    #define MERGE(B1, I1, B2, OFFX)                                          \
        do {                                                                 \
            float o1 = __shfl_xor_sync(0xffffffffu, B1, OFFX);               \
            int  oi1 = __shfl_xor_sync(0xffffffffu, I1, OFFX);               \
            float o2 = __shfl_xor_sync(0xffffffffu, B2, OFFX);               \
            bool t1 = (o1 < B1) || (o1 == B1 && oi1 < I1);                   \
            float hi = fmaxf(B1, o1);                                        \
            B2 = fminf(fminf(B2, o2), hi);                                   \
            B1 = fminf(B1, o1);                                              \
            I1 = t1 ? oi1 : I1;                                              \
        } while (0)
    MERGE(b1a, i1a, b2a, 1);
    MERGE(b1a, i1a, b2a, 2);
    MERGE(b1b, i1b, b2b, 1);
    MERGE(b1b, i1b, b2b, 2);
    #undef MERGE

    if ((lane & 3) == 0) {
        int q  = lane >> 2;
        int rA = warpRow + q;
        int rB = warpRow + q + 8;
        rowcode[rA] = i1a;
        rowcode[rB] = i1b;
        size_t pA = IDX_OFF + (size_t)(rowBase + rA);
        size_t pB = IDX_OFF + (size_t)(rowBase + rB);
        if (pA < (size_t)out_size) out[pA] = (float)i1a;
        if (pB < (size_t)out_size) out[pB] = (float)i1b;
        if (b2a - b1a < BAND_T) flaglist[atomicAdd(flagcnt, 1)] = rA;
        if (b2b - b1b < BAND_T) flaglist[atomicAdd(flagcnt, 1)] = rB;
    }
    __syncthreads();

    // ---- exact fp32 full rescan of flagged rows, one warp per row ----
    {
        int nflag = *flagcnt;
        for (int f = warp; f < nflag; f += 8) {
            int r = flaglist[f];
            const float* xr = X + (size_t)(rowBase + r) * DIM;
            float4 acc4[4];
            #pragma unroll
            for (int j = 0; j < 4; ++j) acc4[j] = make_float4(0.f, 0.f, 0.f, 0.f);
            for (int d = 0; d < DIM; ++d) {
                float xd = xr[d];
                #pragma unroll
                for (int j = 0; j < 4; ++j) {
                    float4 ev = *reinterpret_cast<const float4*>(
                        E + (size_t)d * KCODES + j * 128 + lane * 4);
                    acc4[j].x = fmaf(xd, ev.x, acc4[j].x);
                    acc4[j].y = fmaf(xd, ev.y, acc4[j].y);
                    acc4[j].z = fmaf(xd, ev.z, acc4[j].z);
                    acc4[j].w = fmaf(xd, ev.w, acc4[j].w);
                }
            }
            float bv = CUDART_INF_F;
            int   bi = 0;
            #pragma unroll
            for (int j = 0; j < 4; ++j) {
                float dv[4] = {acc4[j].x, acc4[j].y, acc4[j].z, acc4[j].w};
                #pragma unroll
                for (int e = 0; e < 4; ++e) {
                    int   c = j * 128 + lane * 4 + e;
                    float v = fmaf(-2.f, dv[e], enorm_s[c]);
                    if (v < bv) { bv = v; bi = c; }
                }
            }
            #pragma unroll
            for (int s = 16; s > 0; s >>= 1) {
                float ov = __shfl_xor_sync(0xffffffffu, bv, s);
                int   oi = __shfl_xor_sync(0xffffffffu, bi, s);
                if (ov < bv || (ov == bv && oi < bi)) { bv = ov; bi = oi; }
            }
            if (lane == 0) {
                rowcode[r] = bi;
                size_t p = IDX_OFF + (size_t)(rowBase + r);
                if (p < (size_t)out_size) out[p] = (float)bi;
            }
        }
    }
    __syncthreads();

    // ---- gather quantized (fp32 E), write out, partial loss ----
    float lsum = 0.f;
    #pragma unroll 4
    for (int i = tid; i < ROWS_BLK * DIM; i += THREADS) {
        int r = i >> 6, d = i & 63;
        int code = rowcode[r];
        float qv = E[(size_t)d * KCODES + code];
        float xv = X[(size_t)(rowBase + r) * DIM + d];
        out[(size_t)(rowBase + r) * DIM + d] = qv;
        float df = qv - xv;
        lsum = fmaf(df, df, lsum);
    }

    __syncthreads();
    float* red = reinterpret_cast<float*>(smem + OFF_A);   // A dead now
    red[tid] = lsum;
    __syncthreads();
    #pragma unroll
    for (int s = THREADS / 2; s > 0; s >>= 1) {
        if (tid < s) red[tid] += red[tid + s];
        __syncthreads();
    }

    // ---- last-block deterministic final loss reduction ----
    __shared__ int islast;
    if (tid == 0) {
        g_partials[blockIdx.x] = red[0];
        __threadfence();
        int t = atomicAdd(&g_done, 1);
        islast = (t == NBLOCKS - 1) ? 1 : 0;
    }
    __syncthreads();
    if (islast) {
        volatile float* gp = g_partials;
        float s = 0.f;
        for (int i = tid; i < NBLOCKS; i += THREADS) s += gp[i];
        red[tid] = s;
        __syncthreads();
        #pragma unroll
        for (int st = THREADS / 2; st > 0; st >>= 1) {
            if (tid < st) red[tid] += red[tid + st];
            __syncthreads();
        }
        if (tid == 0) {
            float loss = 1.25f * red[0] / (float)Q_ELEMS;
            if (LOSS_OFF < (size_t)out_size) out[LOSS_OFF] = loss;
            g_done = 0;                     // reset for next graph replay
        }
    }
}

// ---------------------------------------------------------------------------
extern "C" void kernel_launch(void* const* d_in, const int* in_sizes, int n_in,
                              void* d_out, int out_size) {
    const float* X;
    const float* E;
    if (in_sizes[0] == DIM * KCODES && in_sizes[1] != DIM * KCODES) {
        E = (const float*)d_in[0];
        X = (const float*)d_in[1];
    } else {
        X = (const float*)d_in[0];
        E = (const float*)d_in[1];
    }
    float* out = (float*)d_out;
    vq_kernel<<<NBLOCKS, THREADS, SMEM_TOTAL>>>(X, E, out, out_size);
}

// round 7
// speedup vs baseline: 1.0772x; 1.0772x over previous
#include <cuda_runtime.h>
#include <cuda_fp16.h>
#include <math_constants.h>

typedef unsigned int u32;

// Problem: inputs [64,32,32,64] f32 -> N=65536 rows, D=64; embeddings [64,512] f32.
// Output (f32 concat): quantized [N*64] | indices [N] | loss [1]
#define N_ROWS   65536
#define DIM      64
#define KCODES   512
#define ROWS_BLK 128
#define CHUNK    64
#define NCHUNKS  (KCODES / CHUNK)        // 8
#define THREADS  256
#define NBLOCKS  (N_ROWS / ROWS_BLK)     // 512

#define Q_ELEMS  ((size_t)N_ROWS * DIM)
#define IDX_OFF  Q_ELEMS
#define LOSS_OFF (Q_ELEMS + N_ROWS)

// SMEM layout (bytes)
#define ASTRIDE   144                    // 128B fp16 row + 16B pad
#define BSTRIDE   1040                   // 512 codes x 2B + 16B pad (banks shift 4/row)
#define OFF_A     0                                   // 128*144 = 18432
#define OFF_B     (OFF_A + ROWS_BLK * ASTRIDE)        // 18432
#define OFF_ENORM (OFF_B + DIM * BSTRIDE)             // 18432+66560 = 84992
#define OFF_ROWCODE (OFF_ENORM + KCODES * 4)          // 87040
#define OFF_FLAGC (OFF_ROWCODE + ROWS_BLK * 4)        // 87552
#define OFF_FLAGL (OFF_FLAGC + 16)                    // 87568
#define SMEM_TOTAL (OFF_FLAGL + ROWS_BLK * 4 + 16)    // ~88096 -> 2 CTAs/SM

// fp16 error band: dist err <= 2*2^-10*||x||*||e|| <= ~3e-2; flip band ~6e-2.
#define BAND_T 0.09f

__device__ float  g_partials[NBLOCKS];
__device__ int    g_done = 0;
__device__ __half g_Bh[DIM * KCODES];    // fp16 E, [d][code] contiguous
__device__ float  g_enorm[KCODES];

// ---------------------------------------------------------------------------
static __device__ __forceinline__ u32 smem_u32(const void* p) {
    u32 a;
    asm("{ .reg .u64 t; cvta.to.shared.u64 t, %1; cvt.u32.u64 %0, t; }" : "=r"(a) : "l"(p));
    return a;
}
static __device__ __forceinline__ void ldsm_x4(u32& r0, u32& r1, u32& r2, u32& r3, u32 a) {
    asm volatile("ldmatrix.sync.aligned.m8n8.x4.shared.b16 {%0,%1,%2,%3}, [%4];"
                 : "=r"(r0), "=r"(r1), "=r"(r2), "=r"(r3) : "r"(a));
}
static __device__ __forceinline__ void ldsm_x4t(u32& r0, u32& r1, u32& r2, u32& r3, u32 a) {
    asm volatile("ldmatrix.sync.aligned.m8n8.x4.trans.shared.b16 {%0,%1,%2,%3}, [%4];"
                 : "=r"(r0), "=r"(r1), "=r"(r2), "=r"(r3) : "r"(a));
}
static __device__ __forceinline__ void mma_f16(float* c, u32 a0, u32 a1, u32 a2, u32 a3,
                                               u32 b0, u32 b1) {
    asm volatile("mma.sync.aligned.m16n8k16.row.col.f32.f16.f16.f32 "
                 "{%0,%1,%2,%3}, {%4,%5,%6,%7}, {%8,%9}, {%0,%1,%2,%3};"
                 : "+f"(c[0]), "+f"(c[1]), "+f"(c[2]), "+f"(c[3])
                 : "r"(a0), "r"(a1), "r"(a2), "r"(a3), "r"(b0), "r"(b1));
}

// ---------------------------------------------------------------------------
// Kernel 1: prep — fp16 E (coalesced straight copy) + enorm
// ---------------------------------------------------------------------------
__global__ void vq_prep_kernel(const float* __restrict__ E) {
    int gid = blockIdx.x * 512 + threadIdx.x;        // 0..32767 == d*512 + code
    g_Bh[gid] = __float2half_rn(E[gid]);
    if (gid < KCODES) {
        float s = 0.f;
        #pragma unroll 16
        for (int d = 0; d < DIM; ++d) {
            float e = E[(size_t)d * KCODES + gid];
            s = fmaf(e, e, s);
        }
        g_enorm[gid] = s;
    }
}

// ---------------------------------------------------------------------------
// Kernel 2: main — barrier-free mainloop over all 512 codes
// ---------------------------------------------------------------------------
__global__ void __launch_bounds__(THREADS, 2)
vq_kernel(const float* __restrict__ X, const float* __restrict__ E,
          float* __restrict__ out, int out_size) {
    extern __shared__ char smem[];
    const u32 sb   = smem_u32(smem);
    const int tid  = threadIdx.x;
    const int lane = tid & 31;
    const int warp = tid >> 5;
    const int rowBase = blockIdx.x * ROWS_BLK;
    const int warpRow = warp * 16;

    float* enorm_s  = reinterpret_cast<float*>(smem + OFF_ENORM);
    int*   rowcode  = reinterpret_cast<int*>(smem + OFF_ROWCODE);
    int*   flagcnt  = reinterpret_cast<int*>(smem + OFF_FLAGC);
    int*   flaglist = reinterpret_cast<int*>(smem + OFF_FLAGL);

    if (tid == 0) *flagcnt = 0;

    // ---- A tile: fp32 -> fp16, [row][d] stride 144 ----
    #pragma unroll
    for (int it = 0; it < 4; ++it) {
        int task = tid + THREADS * it;            // 1024 tasks: 128 rows x 8 groups
        int r  = task >> 3;
        int d0 = (task & 7) * 8;
        const float4* xv = reinterpret_cast<const float4*>(
            X + (size_t)(rowBase + r) * DIM + d0);
        float4 v0 = xv[0], v1 = xv[1];
        float vals[8] = {v0.x, v0.y, v0.z, v0.w, v1.x, v1.y, v1.z, v1.w};
        union { __half h[8]; uint4 u; } ph;
        #pragma unroll
        for (int e = 0; e < 8; ++e) ph.h[e] = __float2half_rn(vals[e]);
        *reinterpret_cast<uint4*>(smem + OFF_A + r * ASTRIDE + d0 * 2) = ph.u;
    }

    // ---- B: straight copy of all 512 codes (fp16, [d][code] stride 1040) ----
    {
        const uint4* src = reinterpret_cast<const uint4*>(g_Bh);
        #pragma unroll
        for (int it = 0; it < 16; ++it) {
            int i = tid + THREADS * it;           // 4096 uint4: 64 d x 64 groups
            int d = i >> 6, q = i & 63;
            *reinterpret_cast<uint4*>(smem + OFF_B + d * BSTRIDE + q * 16) = src[i];
        }
    }
    // ---- enorm copy ----
    #pragma unroll
    for (int it = 0; it < 2; ++it) {
        int k = tid + THREADS * it;
        enorm_s[k] = g_enorm[k];
    }
    __syncthreads();      // the ONLY barrier before the epilogue

    // ---- hoisted A fragments (chunk-invariant) ----
    const int mA = lane >> 3, rA8 = lane & 7;
    const u32 aBase = sb + OFF_A + (u32)((warpRow + (mA & 1) * 8 + rA8) * ASTRIDE
                                         + (mA >> 1) * 16);
    u32 af[4][4];
    #pragma unroll
    for (int ks = 0; ks < 4; ++ks)
        ldsm_x4(af[ks][0], af[ks][1], af[ks][2], af[ks][3], aBase + ks * 32);

    // B ldmatrix base: lanes 0-15 -> d-rows, lanes 16-31 -> +8 codes
    const u32 bBase = sb + OFF_B + (u32)((lane & 15) * BSTRIDE + (lane >> 4) * 16);

    // top-2 values + top-1 index, two rows per thread
    float b1a = CUDART_INF_F, b2a = CUDART_INF_F;
    float b1b = CUDART_INF_F, b2b = CUDART_INF_F;
    int   i1a = 0, i1b = 0;

    #pragma unroll 2
    for (int ch = 0; ch < NCHUNKS; ++ch) {
        const int c0 = ch * CHUNK;
        float acc[8][4];
        #pragma unroll
        for (int nt = 0; nt < 8; ++nt)
            #pragma unroll
            for (int j = 0; j < 4; ++j) acc[nt][j] = 0.f;

        #pragma unroll
        for (int ks = 0; ks < 4; ++ks) {
            const u32 rowOff = bBase + (u32)(ks * 16 * BSTRIDE) + (u32)(c0 * 2);
            #pragma unroll
            for (int nt2 = 0; nt2 < 4; ++nt2) {
                u32 b0, b1, b2, b3;
                ldsm_x4t(b0, b1, b2, b3, rowOff + nt2 * 32);
                mma_f16(acc[nt2 * 2 + 0], af[ks][0], af[ks][1], af[ks][2], af[ks][3], b0, b1);
                mma_f16(acc[nt2 * 2 + 1], af[ks][0], af[ks][1], af[ks][2], af[ks][3], b2, b3);
            }
        }

        // running top-2 argmin (codes ascend -> lowest index wins ties)
        const int colBase = 2 * (lane & 3);
        #pragma unroll
        for (int nt = 0; nt < 8; ++nt) {
            int   code0 = c0 + nt * 8 + colBase;
            float e0 = enorm_s[code0], e1 = enorm_s[code0 + 1];
            float v;
            #define UPD(B1, I1, B2, VAL, IDX)                        \
                do { v = (VAL);                                      \
                     bool p = v < B1;                                \
                     B2 = fminf(B2, fmaxf(v, B1));                   \
                     B1 = fminf(B1, v);                              \
                     I1 = p ? (IDX) : I1; } while (0)
            UPD(b1a, i1a, b2a, fmaf(-2.f, acc[nt][0], e0), code0);
            UPD(b1a, i1a, b2a, fmaf(-2.f, acc[nt][1], e1), code0 + 1);
            UPD(b1b, i1b, b2b, fmaf(-2.f, acc[nt][2], e0), code0);
            UPD(b1b, i1b, b2b, fmaf(-2.f, acc[nt][3], e1), code0 + 1);
            #undef UPD
        }
    }

    // ---- cross-lane merge within quad (top-2 values + top-1 index) ----
    #define MERGE(B1, I1, B2, OFFX)                                          \
        do {                                                                 \
            float o1 = __shfl_xor_sync(0xffffffffu, B1, OFFX);               \
            int  oi1 = __shfl_xor_sync(0xffffffffu, I1, OFFX);               \
            float o2 = __shfl_xor_sync(0xffffffffu, B2, OFFX);               \
            bool t1 = (o1 < B1) || (o1 == B1 && oi1 < I1);                   \
            float hi = fmaxf(B1, o1);                                        \
            B2 = fminf(fminf(B2, o2), hi);                                   \
            B1 = fminf(B1, o1);                                              \
            I1 = t1 ? oi1 : I1;                                              \
        } while (0)
    MERGE(b1a, i1a, b2a, 1);
    MERGE(b1a, i1a, b2a, 2);
    MERGE(b1b, i1b, b2b, 1);
    MERGE(b1b, i1b, b2b, 2);
    #undef MERGE

    if ((lane & 3) == 0) {
        int q  = lane >> 2;
        int rA = warpRow + q;
        int rB = warpRow + q + 8;
        rowcode[rA] = i1a;
        rowcode[rB] = i1b;
        size_t pA = IDX_OFF + (size_t)(rowBase + rA);
        size_t pB = IDX_OFF + (size_t)(rowBase + rB);
        if (pA < (size_t)out_size) out[pA] = (float)i1a;
        if (pB < (size_t)out_size) out[pB] = (float)i1b;
        if (b2a - b1a < BAND_T) flaglist[atomicAdd(flagcnt, 1)] = rA;
        if (b2b - b1b < BAND_T) flaglist[atomicAdd(flagcnt, 1)] = rB;
    }
    __syncthreads();

    // ---- exact fp32 full rescan of flagged rows, one warp per row ----
    {
        int nflag = *flagcnt;
        for (int f = warp; f < nflag; f += 8) {
            int r = flaglist[f];
            const float* xr = X + (size_t)(rowBase + r) * DIM;
            float4 acc4[4];
            #pragma unroll
            for (int j = 0; j < 4; ++j) acc4[j] = make_float4(0.f, 0.f, 0.f, 0.f);
            for (int d = 0; d < DIM; ++d) {
                float xd = xr[d];
                #pragma unroll
                for (int j = 0; j < 4; ++j) {
                    float4 ev = *reinterpret_cast<const float4*>(
                        E + (size_t)d * KCODES + j * 128 + lane * 4);
                    acc4[j].x = fmaf(xd, ev.x, acc4[j].x);
                    acc4[j].y = fmaf(xd, ev.y, acc4[j].y);
                    acc4[j].z = fmaf(xd, ev.z, acc4[j].z);
                    acc4[j].w = fmaf(xd, ev.w, acc4[j].w);
                }
            }
            float bv = CUDART_INF_F;
            int   bi = 0;
            #pragma unroll
            for (int j = 0; j < 4; ++j) {
                float dv[4] = {acc4[j].x, acc4[j].y, acc4[j].z, acc4[j].w};
                #pragma unroll
                for (int e = 0; e < 4; ++e) {
                    int   c = j * 128 + lane * 4 + e;
                    float v = fmaf(-2.f, dv[e], enorm_s[c]);
                    if (v < bv) { bv = v; bi = c; }
                }
            }
            #pragma unroll
            for (int s = 16; s > 0; s >>= 1) {
                float ov = __shfl_xor_sync(0xffffffffu, bv, s);
                int   oi = __shfl_xor_sync(0xffffffffu, bi, s);
                if (ov < bv || (ov == bv && oi < bi)) { bv = ov; bi = oi; }
            }
            if (lane == 0) {
                rowcode[r] = bi;
                size_t p = IDX_OFF + (size_t)(rowBase + r);
                if (p < (size_t)out_size) out[p] = (float)bi;
            }
        }
    }
    __syncthreads();

    // ---- gather quantized (fp32 E), write out, partial loss ----
    float lsum = 0.f;
    #pragma unroll 4
    for (int i = tid; i < ROWS_BLK * DIM; i += THREADS) {
        int r = i >> 6, d = i & 63;
        int code = rowcode[r];
        float qv = E[(size_t)d * KCODES + code];
        float xv = X[(size_t)(rowBase + r) * DIM + d];
        out[(size_t)(rowBase + r) * DIM + d] = qv;
        float df = qv - xv;
        lsum = fmaf(df, df, lsum);
    }

    __syncthreads();
    float* red = reinterpret_cast<float*>(smem + OFF_A);   // A dead now
    red[tid] = lsum;
    __syncthreads();
    #pragma unroll
    for (int s = THREADS / 2; s > 0; s >>= 1) {
        if (tid < s) red[tid] += red[tid + s];
        __syncthreads();
    }

    // ---- last-block deterministic final loss reduction ----
    __shared__ int islast;
    if (tid == 0) {
        g_partials[blockIdx.x] = red[0];
        __threadfence();
        int t = atomicAdd(&g_done, 1);
        islast = (t == NBLOCKS - 1) ? 1 : 0;
    }
    __syncthreads();
    if (islast) {
        volatile float* gp = g_partials;
        float s = 0.f;
        for (int i = tid; i < NBLOCKS; i += THREADS) s += gp[i];
        red[tid] = s;
        __syncthreads();
        #pragma unroll
        for (int st = THREADS / 2; st > 0; st >>= 1) {
            if (tid < st) red[tid] += red[tid + st];
            __syncthreads();
        }
        if (tid == 0) {
            float loss = 1.25f * red[0] / (float)Q_ELEMS;
            if (LOSS_OFF < (size_t)out_size) out[LOSS_OFF] = loss;
            g_done = 0;                     // reset for next graph replay
        }
    }
}

// ---------------------------------------------------------------------------
extern "C" void kernel_launch(void* const* d_in, const int* in_sizes, int n_in,
                              void* d_out, int out_size) {
    const float* X;
    const float* E;
    if (in_sizes[0] == DIM * KCODES && in_sizes[1] != DIM * KCODES) {
        E = (const float*)d_in[0];
        X = (const float*)d_in[1];
    } else {
        X = (const float*)d_in[0];
        E = (const float*)d_in[1];
    }
    float* out = (float*)d_out;

    static bool attr_done = false;
    if (!attr_done) {
        cudaFuncSetAttribute(vq_kernel,
                             cudaFuncAttributeMaxDynamicSharedMemorySize, SMEM_TOTAL);
        attr_done = true;
    }

    vq_prep_kernel<<<64, 512>>>(E);
    vq_kernel<<<NBLOCKS, THREADS, SMEM_TOTAL>>>(X, E, out, out_size);
}

// round 8
// speedup vs baseline: 1.1454x; 1.0633x over previous
#include <cuda_runtime.h>
#include <cuda_fp16.h>
#include <math_constants.h>

typedef unsigned int u32;

// Problem: inputs [64,32,32,64] f32 -> N=65536 rows, D=64; embeddings [64,512] f32.
// Output (f32 concat): quantized [N*64] | indices [N] | loss [1]
#define N_ROWS   65536
#define DIM      64
#define KCODES   512
#define ROWS_BLK 128
#define CHUNK    64
#define NCHUNKS  (KCODES / CHUNK)        // 8
#define THREADS  256
#define NTILES   (N_ROWS / ROWS_BLK)     // 512
#define NCTAS    256                     // each CTA: tiles bid, bid+256

#define Q_ELEMS  ((size_t)N_ROWS * DIM)
#define IDX_OFF  Q_ELEMS
#define LOSS_OFF (Q_ELEMS + N_ROWS)

// SMEM layout (bytes)
#define ASTRIDE   144                    // 128B fp16 row + 16B pad
#define BSTRIDE   1040                   // 512 codes x 2B + 16B pad
#define OFF_A0    0                                   // 18432
#define OFF_A1    (OFF_A0 + ROWS_BLK * ASTRIDE)       // 18432
#define OFF_B     (OFF_A1 + ROWS_BLK * ASTRIDE)       // 36864
#define OFF_ENORM (OFF_B + DIM * BSTRIDE)             // 103424
#define OFF_ROWCODE (OFF_ENORM + KCODES * 4)          // 105472
#define OFF_FLAGC (OFF_ROWCODE + ROWS_BLK * 4)        // 105984
#define OFF_FLAGL (OFF_FLAGC + 16)                    // 106000
#define SMEM_TOTAL (OFF_FLAGL + ROWS_BLK * 4 + 16)    // ~106528 -> 2 CTAs/SM

// fp16 error band: dist err <= 2*2^-10*||x||*||e|| <= ~3e-2; flip band ~6e-2.
#define BAND_T 0.09f

__device__ float  g_partials[NCTAS];
__device__ int    g_done = 0;
__device__ __half g_Bh[DIM * KCODES];    // fp16 E, [d][code]
__device__ float  g_ET[KCODES * DIM];    // fp32 E transposed, [code][d]
__device__ float  g_enorm[KCODES];

// ---------------------------------------------------------------------------
static __device__ __forceinline__ u32 smem_u32(const void* p) {
    u32 a;
    asm("{ .reg .u64 t; cvta.to.shared.u64 t, %1; cvt.u32.u64 %0, t; }" : "=r"(a) : "l"(p));
    return a;
}
static __device__ __forceinline__ void ldsm_x4(u32& r0, u32& r1, u32& r2, u32& r3, u32 a) {
    asm volatile("ldmatrix.sync.aligned.m8n8.x4.shared.b16 {%0,%1,%2,%3}, [%4];"
                 : "=r"(r0), "=r"(r1), "=r"(r2), "=r"(r3) : "r"(a));
}
static __device__ __forceinline__ void ldsm_x4t(u32& r0, u32& r1, u32& r2, u32& r3, u32 a) {
    asm volatile("ldmatrix.sync.aligned.m8n8.x4.trans.shared.b16 {%0,%1,%2,%3}, [%4];"
                 : "=r"(r0), "=r"(r1), "=r"(r2), "=r"(r3) : "r"(a));
}
static __device__ __forceinline__ void mma_f16(float* c, u32 a0, u32 a1, u32 a2, u32 a3,
                                               u32 b0, u32 b1) {
    asm volatile("mma.sync.aligned.m16n8k16.row.col.f32.f16.f16.f32 "
                 "{%0,%1,%2,%3}, {%4,%5,%6,%7}, {%8,%9}, {%0,%1,%2,%3};"
                 : "+f"(c[0]), "+f"(c[1]), "+f"(c[2]), "+f"(c[3])
                 : "r"(a0), "r"(a1), "r"(a2), "r"(a3), "r"(b0), "r"(b1));
}

// ---------------------------------------------------------------------------
// Kernel 1: prep — fp16 E, transposed fp32 E, enorm
// ---------------------------------------------------------------------------
__global__ void vq_prep_kernel(const float* __restrict__ E) {
    int gid = blockIdx.x * 512 + threadIdx.x;        // 0..32767 == d*512 + code
    float v = E[gid];
    g_Bh[gid] = __float2half_rn(v);
    int d = gid >> 9, c = gid & 511;
    g_ET[c * DIM + d] = v;                           // scattered 4B writes; tiny kernel
    if (gid < KCODES) {
        float s = 0.f;
        #pragma unroll 16
        for (int dd = 0; dd < DIM; ++dd) {
            float e = E[(size_t)dd * KCODES + gid];
            s = fmaf(e, e, s);
        }
        g_enorm[gid] = s;
    }
}

// ---------------------------------------------------------------------------
// A tile loader: fp32 X -> fp16 smem [row][d] stride 144
// ---------------------------------------------------------------------------
static __device__ __forceinline__ void load_A(const float* __restrict__ X,
                                              char* smem, int dstOff,
                                              int rowBase, int tid) {
    #pragma unroll
    for (int it = 0; it < 4; ++it) {
        int task = tid + THREADS * it;            // 1024 tasks: 128 rows x 8 groups
        int r  = task >> 3;
        int d0 = (task & 7) * 8;
        const float4* xv = reinterpret_cast<const float4*>(
            X + (size_t)(rowBase + r) * DIM + d0);
        float4 v0 = xv[0], v1 = xv[1];
        float vals[8] = {v0.x, v0.y, v0.z, v0.w, v1.x, v1.y, v1.z, v1.w};
        union { __half h[8]; uint4 u; } ph;
        #pragma unroll
        for (int e = 0; e < 8; ++e) ph.h[e] = __float2half_rn(vals[e]);
        *reinterpret_cast<uint4*>(smem + dstOff + r * ASTRIDE + d0 * 2) = ph.u;
    }
}

// ---------------------------------------------------------------------------
// Kernel 2: persistent main — 2 row-tiles per CTA, B staged once
// ---------------------------------------------------------------------------
__global__ void __launch_bounds__(THREADS, 2)
vq_kernel(const float* __restrict__ X, const float* __restrict__ E,
          float* __restrict__ out, int out_size) {
    extern __shared__ char smem[];
    const u32 sb   = smem_u32(smem);
    const int tid  = threadIdx.x;
    const int lane = tid & 31;
    const int warp = tid >> 5;
    const int warpRow = warp * 16;

    float* enorm_s  = reinterpret_cast<float*>(smem + OFF_ENORM);
    int*   rowcode  = reinterpret_cast<int*>(smem + OFF_ROWCODE);
    int*   flagcnt  = reinterpret_cast<int*>(smem + OFF_FLAGC);
    int*   flaglist = reinterpret_cast<int*>(smem + OFF_FLAGL);

    if (tid == 0) *flagcnt = 0;

    // ---- one-time staging: B (all 512 codes), enorm, A for tile 0 ----
    {
        const uint4* src = reinterpret_cast<const uint4*>(g_Bh);
        #pragma unroll
        for (int it = 0; it < 16; ++it) {
            int i = tid + THREADS * it;           // 4096 uint4: 64 d x 64 groups
            int d = i >> 6, q = i & 63;
            *reinterpret_cast<uint4*>(smem + OFF_B + d * BSTRIDE + q * 16) = src[i];
        }
    }
    #pragma unroll
    for (int it = 0; it < 2; ++it) {
        int k = tid + THREADS * it;
        enorm_s[k] = g_enorm[k];
    }
    load_A(X, smem, OFF_A0, blockIdx.x * ROWS_BLK, tid);
    __syncthreads();

    // B ldmatrix base: lanes 0-15 -> d-rows, lanes 16-31 -> +8 codes
    const u32 bBase = sb + OFF_B + (u32)((lane & 15) * BSTRIDE + (lane >> 4) * 16);
    const int mA = lane >> 3, rA8 = lane & 7;
    const u32 aFragOff = (u32)((warpRow + (mA & 1) * 8 + rA8) * ASTRIDE + (mA >> 1) * 16);

    float lsum = 0.f;

    #pragma unroll 1
    for (int t = 0; t < 2; ++t) {
        const int tile    = blockIdx.x + t * NCTAS;
        const int rowBase = tile * ROWS_BLK;
        const u32 aBase   = sb + (t ? OFF_A1 : OFF_A0) + aFragOff;

        // ---- hoisted A fragments ----
        u32 af[4][4];
        #pragma unroll
        for (int ks = 0; ks < 4; ++ks)
            ldsm_x4(af[ks][0], af[ks][1], af[ks][2], af[ks][3], aBase + ks * 32);

        // top-2 values + top-1 index, two rows per thread
        float b1a = CUDART_INF_F, b2a = CUDART_INF_F;
        float b1b = CUDART_INF_F, b2b = CUDART_INF_F;
        int   i1a = 0, i1b = 0;

        #pragma unroll 2
        for (int ch = 0; ch < NCHUNKS; ++ch) {
            const int c0 = ch * CHUNK;
            float acc[8][4];
            #pragma unroll
            for (int nt = 0; nt < 8; ++nt)
                #pragma unroll
                for (int j = 0; j < 4; ++j) acc[nt][j] = 0.f;

            #pragma unroll
            for (int ks = 0; ks < 4; ++ks) {
                const u32 rowOff = bBase + (u32)(ks * 16 * BSTRIDE) + (u32)(c0 * 2);
                #pragma unroll
                for (int nt2 = 0; nt2 < 4; ++nt2) {
                    u32 b0, b1, b2, b3;
                    ldsm_x4t(b0, b1, b2, b3, rowOff + nt2 * 32);
                    mma_f16(acc[nt2 * 2 + 0], af[ks][0], af[ks][1], af[ks][2], af[ks][3], b0, b1);
                    mma_f16(acc[nt2 * 2 + 1], af[ks][0], af[ks][1], af[ks][2], af[ks][3], b2, b3);
                }
            }

            // running top-2 argmin (codes ascend -> lowest index wins ties)
            const int colBase = 2 * (lane & 3);
            #pragma unroll
            for (int nt = 0; nt < 8; ++nt) {
                int   code0 = c0 + nt * 8 + colBase;
                float e0 = enorm_s[code0], e1 = enorm_s[code0 + 1];
                float v;
                #define UPD(B1, I1, B2, VAL, IDX)                        \
                    do { v = (VAL);                                      \
                         bool p = v < B1;                                \
                         B2 = fminf(B2, fmaxf(v, B1));                   \
                         B1 = fminf(B1, v);                              \
                         I1 = p ? (IDX) : I1; } while (0)
                UPD(b1a, i1a, b2a, fmaf(-2.f, acc[nt][0], e0), code0);
                UPD(b1a, i1a, b2a, fmaf(-2.f, acc[nt][1], e1), code0 + 1);
                UPD(b1b, i1b, b2b, fmaf(-2.f, acc[nt][2], e0), code0);
                UPD(b1b, i1b, b2b, fmaf(-2.f, acc[nt][3], e1), code0 + 1);
                #undef UPD
            }
        }

        // ---- prefetch next tile's A (overlaps epilogue below) ----
        if (t == 0)
            load_A(X, smem, OFF_A1, (blockIdx.x + NCTAS) * ROWS_BLK, tid);

        // ---- cross-lane merge within quad ----
        #define MERGE(B1, I1, B2, OFFX)                                          \
            do {                                                                 \
                float o1 = __shfl_xor_sync(0xffffffffu, B1, OFFX);               \
                int  oi1 = __shfl_xor_sync(0xffffffffu, I1, OFFX);               \
                float o2 = __shfl_xor_sync(0xffffffffu, B2, OFFX);               \
                bool t1 = (o1 < B1) || (o1 == B1 && oi1 < I1);                   \
                float hi = fmaxf(B1, o1);                                        \
                B2 = fminf(fminf(B2, o2), hi);                                   \
                B1 = fminf(B1, o1);                                              \
                I1 = t1 ? oi1 : I1;                                              \
            } while (0)
        MERGE(b1a, i1a, b2a, 1);
        MERGE(b1a, i1a, b2a, 2);
        MERGE(b1b, i1b, b2b, 1);
        MERGE(b1b, i1b, b2b, 2);
        #undef MERGE

        if ((lane & 3) == 0) {
            int q  = lane >> 2;
            int rA = warpRow + q;
            int rB = warpRow + q + 8;
            rowcode[rA] = i1a;
            rowcode[rB] = i1b;
            size_t pA = IDX_OFF + (size_t)(rowBase + rA);
            size_t pB = IDX_OFF + (size_t)(rowBase + rB);
            if (pA < (size_t)out_size) out[pA] = (float)i1a;
            if (pB < (size_t)out_size) out[pB] = (float)i1b;
            if (b2a - b1a < BAND_T) flaglist[atomicAdd(flagcnt, 1)] = rA;
            if (b2b - b1b < BAND_T) flaglist[atomicAdd(flagcnt, 1)] = rB;
        }
        __syncthreads();

        // ---- exact fp32 full rescan of flagged rows, one warp per row ----
        {
            int nflag = *flagcnt;
            for (int f = warp; f < nflag; f += 8) {
                int r = flaglist[f];
                const float* xr = X + (size_t)(rowBase + r) * DIM;
                float4 acc4[4];
                #pragma unroll
                for (int j = 0; j < 4; ++j) acc4[j] = make_float4(0.f, 0.f, 0.f, 0.f);
                for (int d = 0; d < DIM; ++d) {
                    float xd = xr[d];
                    #pragma unroll
                    for (int j = 0; j < 4; ++j) {
                        float4 ev = *reinterpret_cast<const float4*>(
                            E + (size_t)d * KCODES + j * 128 + lane * 4);
                        acc4[j].x = fmaf(xd, ev.x, acc4[j].x);
                        acc4[j].y = fmaf(xd, ev.y, acc4[j].y);
                        acc4[j].z = fmaf(xd, ev.z, acc4[j].z);
                        acc4[j].w = fmaf(xd, ev.w, acc4[j].w);
                    }
                }
                float bv = CUDART_INF_F;
                int   bi = 0;
                #pragma unroll
                for (int j = 0; j < 4; ++j) {
                    float dv[4] = {acc4[j].x, acc4[j].y, acc4[j].z, acc4[j].w};
                    #pragma unroll
                    for (int e = 0; e < 4; ++e) {
                        int   c = j * 128 + lane * 4 + e;
                        float v = fmaf(-2.f, dv[e], enorm_s[c]);
                        if (v < bv) { bv = v; bi = c; }
                    }
                }
                #pragma unroll
                for (int s = 16; s > 0; s >>= 1) {
                    float ov = __shfl_xor_sync(0xffffffffu, bv, s);
                    int   oi = __shfl_xor_sync(0xffffffffu, bi, s);
                    if (ov < bv || (ov == bv && oi < bi)) { bv = ov; bi = oi; }
                }
                if (lane == 0) {
                    rowcode[r] = bi;
                    size_t p = IDX_OFF + (size_t)(rowBase + r);
                    if (p < (size_t)out_size) out[p] = (float)bi;
                }
            }
        }
        __syncthreads();
        if (tid == 0) *flagcnt = 0;     // reset (ordered by the sync below)

        // ---- gather quantized via transposed ET (coalesced), loss ----
        #pragma unroll 4
        for (int i = tid; i < ROWS_BLK * DIM; i += THREADS) {
            int r = i >> 6, d = i & 63;
            int code = rowcode[r];
            float qv = g_ET[code * DIM + d];
            float xv = X[(size_t)(rowBase + r) * DIM + d];
            out[(size_t)(rowBase + r) * DIM + d] = qv;
            float df = qv - xv;
            lsum = fmaf(df, df, lsum);
        }
        __syncthreads();     // rowcode/flagcnt safe for next tile; A1 staged
    }

    // ---- block loss reduction ----
    float* red = reinterpret_cast<float*>(smem + OFF_A0);   // A dead now
    red[tid] = lsum;
    __syncthreads();
    #pragma unroll
    for (int s = THREADS / 2; s > 0; s >>= 1) {
        if (tid < s) red[tid] += red[tid + s];
        __syncthreads();
    }

    // ---- last-block deterministic final loss reduction ----
    __shared__ int islast;
    if (tid == 0) {
        g_partials[blockIdx.x] = red[0];
        __threadfence();
        int tk = atomicAdd(&g_done, 1);
        islast = (tk == NCTAS - 1) ? 1 : 0;
    }
    __syncthreads();
    if (islast) {
        volatile float* gp = g_partials;
        float s = (tid < NCTAS) ? gp[tid] : 0.f;
        red[tid] = s;
        __syncthreads();
        #pragma unroll
        for (int st = THREADS / 2; st > 0; st >>= 1) {
            if (tid < st) red[tid] += red[tid + st];
            __syncthreads();
        }
        if (tid == 0) {
            float loss = 1.25f * red[0] / (float)Q_ELEMS;
            if (LOSS_OFF < (size_t)out_size) out[LOSS_OFF] = loss;
            g_done = 0;                     // reset for next graph replay
        }
    }
}

// ---------------------------------------------------------------------------
extern "C" void kernel_launch(void* const* d_in, const int* in_sizes, int n_in,
                              void* d_out, int out_size) {
    const float* X;
    const float* E;
    if (in_sizes[0] == DIM * KCODES && in_sizes[1] != DIM * KCODES) {
        E = (const float*)d_in[0];
        X = (const float*)d_in[1];
    } else {
        X = (const float*)d_in[0];
        E = (const float*)d_in[1];
    }
    float* out = (float*)d_out;

    static bool attr_done = false;
    if (!attr_done) {
        cudaFuncSetAttribute(vq_kernel,
                             cudaFuncAttributeMaxDynamicSharedMemorySize, SMEM_TOTAL);
        attr_done = true;
    }

    vq_prep_kernel<<<64, 512>>>(E);
    vq_kernel<<<NCTAS, THREADS, SMEM_TOTAL>>>(X, E, out, out_size);
}

// round 9
// speedup vs baseline: 1.2395x; 1.0821x over previous
#include <cuda_runtime.h>
#include <cuda_fp16.h>
#include <math_constants.h>

typedef unsigned int u32;

// Problem: inputs [64,32,32,64] f32 -> N=65536 rows, D=64; embeddings [64,512] f32.
// Output (f32 concat): quantized [N*64] | indices [N] | loss [1]
#define N_ROWS   65536
#define DIM      64
#define KCODES   512
#define ROWS_BLK 256
#define THREADS  512
#define NCTAS    (N_ROWS / ROWS_BLK)     // 256 CTAs, single wave

#define Q_ELEMS  ((size_t)N_ROWS * DIM)
#define IDX_OFF  Q_ELEMS
#define LOSS_OFF (Q_ELEMS + N_ROWS)

// SMEM layout (bytes)
#define ASTRIDE   144                    // 128B fp16 row + 16B pad
#define BSTRIDE   1040                   // 512 codes x 2B + 16B pad
#define OFF_A     0                                   // 256*144 = 36864
#define OFF_B     (OFF_A + ROWS_BLK * ASTRIDE)        // 36864
#define OFF_ENORM (OFF_B + DIM * BSTRIDE)             // 103424
#define OFF_ROWCODE (OFF_ENORM + KCODES * 4)          // 105472
#define OFF_FLAGC (OFF_ROWCODE + ROWS_BLK * 4)        // 106496
#define OFF_FLAGL (OFF_FLAGC + 16)                    // 106512
#define SMEM_TOTAL (OFF_FLAGL + ROWS_BLK * 4 + 16)    // ~107552 -> 2 CTAs/SM

// fp16 flip band ~0.032 + packing error <0.001 -> 0.09 is ample.
#define BAND_T 0.09f

__device__ float  g_partials[NCTAS];
__device__ int    g_done = 0;
__device__ __half g_Bh[DIM * KCODES];    // fp16 E, [d][code]
__device__ float  g_ET[KCODES * DIM];    // fp32 E transposed, [code][d]
__device__ float  g_enorm[KCODES];

// ---------------------------------------------------------------------------
static __device__ __forceinline__ u32 smem_u32(const void* p) {
    u32 a;
    asm("{ .reg .u64 t; cvta.to.shared.u64 t, %1; cvt.u32.u64 %0, t; }" : "=r"(a) : "l"(p));
    return a;
}
static __device__ __forceinline__ void ldsm_x4(u32& r0, u32& r1, u32& r2, u32& r3, u32 a) {
    asm volatile("ldmatrix.sync.aligned.m8n8.x4.shared.b16 {%0,%1,%2,%3}, [%4];"
                 : "=r"(r0), "=r"(r1), "=r"(r2), "=r"(r3) : "r"(a));
}
static __device__ __forceinline__ void ldsm_x4t(u32& r0, u32& r1, u32& r2, u32& r3, u32 a) {
    asm volatile("ldmatrix.sync.aligned.m8n8.x4.trans.shared.b16 {%0,%1,%2,%3}, [%4];"
                 : "=r"(r0), "=r"(r1), "=r"(r2), "=r"(r3) : "r"(a));
}
static __device__ __forceinline__ void mma_f16(float* c, const u32* a, u32 b0, u32 b1) {
    asm volatile("mma.sync.aligned.m16n8k16.row.col.f32.f16.f16.f32 "
                 "{%0,%1,%2,%3}, {%4,%5,%6,%7}, {%8,%9}, {%0,%1,%2,%3};"
                 : "+f"(c[0]), "+f"(c[1]), "+f"(c[2]), "+f"(c[3])
                 : "r"(a[0]), "r"(a[1]), "r"(a[2]), "r"(a[3]), "r"(b0), "r"(b1));
}
// pack code into low 9 mantissa bits of distance (|dist|<16 -> error < 1e-3)
static __device__ __forceinline__ float packkey(float v, int code) {
    return __uint_as_float((__float_as_uint(v) & 0xFFFFFE00u) | (u32)code);
}

// ---------------------------------------------------------------------------
// Kernel 1: prep — fp16 E, transposed fp32 E, enorm
// ---------------------------------------------------------------------------
__global__ void vq_prep_kernel(const float* __restrict__ E) {
    int gid = blockIdx.x * 512 + threadIdx.x;        // 0..32767 == d*512 + code
    float v = E[gid];
    g_Bh[gid] = __float2half_rn(v);
    int d = gid >> 9, c = gid & 511;
    g_ET[c * DIM + d] = v;
    if (gid < KCODES) {
        float s = 0.f;
        #pragma unroll 16
        for (int dd = 0; dd < DIM; ++dd) {
            float e = E[(size_t)dd * KCODES + gid];
            s = fmaf(e, e, s);
        }
        g_enorm[gid] = s;
    }
}

// ---------------------------------------------------------------------------
// Kernel 2: main — 512 threads, 256 rows/CTA, packed-key argmin
// ---------------------------------------------------------------------------
__global__ void __launch_bounds__(THREADS, 2)
vq_kernel(const float* __restrict__ X, const float* __restrict__ E,
          float* __restrict__ out, int out_size) {
    extern __shared__ char smem[];
    const u32 sb   = smem_u32(smem);
    const int tid  = threadIdx.x;
    const int lane = tid & 31;
    const int warp = tid >> 5;                // 0..15
    const int rowBase = blockIdx.x * ROWS_BLK;
    const int warpRow = warp * 16;

    float* enorm_s  = reinterpret_cast<float*>(smem + OFF_ENORM);
    int*   rowcode  = reinterpret_cast<int*>(smem + OFF_ROWCODE);
    int*   flagcnt  = reinterpret_cast<int*>(smem + OFF_FLAGC);
    int*   flaglist = reinterpret_cast<int*>(smem + OFF_FLAGL);

    if (tid == 0) *flagcnt = 0;

    // ---- A tile: fp32 -> fp16, [row][d] stride 144 ----
    #pragma unroll
    for (int it = 0; it < 4; ++it) {
        int task = tid + THREADS * it;        // 2048 tasks: 256 rows x 8 groups
        int r  = task >> 3;
        int d0 = (task & 7) * 8;
        const float4* xv = reinterpret_cast<const float4*>(
            X + (size_t)(rowBase + r) * DIM + d0);
        float4 v0 = xv[0], v1 = xv[1];
        float vals[8] = {v0.x, v0.y, v0.z, v0.w, v1.x, v1.y, v1.z, v1.w};
        union { __half h[8]; uint4 u; } ph;
        #pragma unroll
        for (int e = 0; e < 8; ++e) ph.h[e] = __float2half_rn(vals[e]);
        *reinterpret_cast<uint4*>(smem + OFF_A + r * ASTRIDE + d0 * 2) = ph.u;
    }
    // ---- B: copy all 512 codes (fp16, [d][code] stride 1040) ----
    {
        const uint4* src = reinterpret_cast<const uint4*>(g_Bh);
        #pragma unroll
        for (int it = 0; it < 8; ++it) {
            int i = tid + THREADS * it;       // 4096 uint4: 64 d x 64 groups
            int d = i >> 6, q = i & 63;
            *reinterpret_cast<uint4*>(smem + OFF_B + d * BSTRIDE + q * 16) = src[i];
        }
    }
    enorm_s[tid] = g_enorm[tid];
    __syncthreads();

    // ---- hoisted A fragments ----
    const int mA = lane >> 3, rA8 = lane & 7;
    const u32 aBase = sb + OFF_A + (u32)((warpRow + (mA & 1) * 8 + rA8) * ASTRIDE
                                         + (mA >> 1) * 16);
    u32 af[4][4];
    #pragma unroll
    for (int ks = 0; ks < 4; ++ks)
        ldsm_x4(af[ks][0], af[ks][1], af[ks][2], af[ks][3], aBase + ks * 32);

    const u32 bBase = sb + OFF_B + (u32)((lane & 15) * BSTRIDE + (lane >> 4) * 16);

    // packed top-2 keys per row (value + embedded code)
    float k1a = CUDART_INF_F, k2a = CUDART_INF_F;
    float k1b = CUDART_INF_F, k2b = CUDART_INF_F;

    // ---- mainloop: 16 subchunks of 32 codes ----
    #pragma unroll 2
    for (int s = 0; s < 16; ++s) {
        const int c0 = s * 32;
        float acc[4][4];
        #pragma unroll
        for (int nt = 0; nt < 4; ++nt)
            #pragma unroll
            for (int j = 0; j < 4; ++j) acc[nt][j] = 0.f;

        #pragma unroll
        for (int ks = 0; ks < 4; ++ks) {
            const u32 rowOff = bBase + (u32)(ks * 16 * BSTRIDE) + (u32)(c0 * 2);
            u32 b0, b1, b2, b3;
            ldsm_x4t(b0, b1, b2, b3, rowOff);
            mma_f16(acc[0], af[ks], b0, b1);
            mma_f16(acc[1], af[ks], b2, b3);
            ldsm_x4t(b0, b1, b2, b3, rowOff + 32);
            mma_f16(acc[2], af[ks], b0, b1);
            mma_f16(acc[3], af[ks], b2, b3);
        }

        const int colBase = 2 * (lane & 3);
        #pragma unroll
        for (int nt = 0; nt < 4; ++nt) {
            int   code0 = c0 + nt * 8 + colBase;
            float e0 = enorm_s[code0], e1 = enorm_s[code0 + 1];
            float pk;
            #define UPD(K1, K2, VAL, IDX)                            \
                do { pk = packkey((VAL), (IDX));                     \
                     K2 = fminf(K2, fmaxf(K1, pk));                  \
                     K1 = fminf(K1, pk); } while (0)
            UPD(k1a, k2a, fmaf(-2.f, acc[nt][0], e0), code0);
            UPD(k1a, k2a, fmaf(-2.f, acc[nt][1], e1), code0 + 1);
            UPD(k1b, k2b, fmaf(-2.f, acc[nt][2], e0), code0);
            UPD(k1b, k2b, fmaf(-2.f, acc[nt][3], e1), code0 + 1);
            #undef UPD
        }
    }

    // ---- cross-lane top-2 merge within quad (pure float min/max) ----
    #define MERGE(K1, K2, OFFX)                                              \
        do {                                                                 \
            float o1 = __shfl_xor_sync(0xffffffffu, K1, OFFX);               \
            float o2 = __shfl_xor_sync(0xffffffffu, K2, OFFX);               \
            K2 = fminf(fminf(K2, o2), fmaxf(K1, o1));                        \
            K1 = fminf(K1, o1);                                              \
        } while (0)
    MERGE(k1a, k2a, 1);
    MERGE(k1a, k2a, 2);
    MERGE(k1b, k2b, 1);
    MERGE(k1b, k2b, 2);
    #undef MERGE

    if ((lane & 3) == 0) {
        int q  = lane >> 2;
        int rA = warpRow + q;
        int rB = warpRow + q + 8;
        int i1a = (int)(__float_as_uint(k1a) & 511u);
        int i1b = (int)(__float_as_uint(k1b) & 511u);
        rowcode[rA] = i1a;
        rowcode[rB] = i1b;
        size_t pA = IDX_OFF + (size_t)(rowBase + rA);
        size_t pB = IDX_OFF + (size_t)(rowBase + rB);
        if (pA < (size_t)out_size) out[pA] = (float)i1a;
        if (pB < (size_t)out_size) out[pB] = (float)i1b;
        if (k2a - k1a < BAND_T) flaglist[atomicAdd(flagcnt, 1)] = rA;
        if (k2b - k1b < BAND_T) flaglist[atomicAdd(flagcnt, 1)] = rB;
    }
    __syncthreads();

    // ---- exact fp32 full rescan of flagged rows, one warp per row ----
    {
        int nflag = *flagcnt;
        for (int f = warp; f < nflag; f += 16) {
            int r = flaglist[f];
            const float* xr = X + (size_t)(rowBase + r) * DIM;
            float4 acc4[4];
            #pragma unroll
            for (int j = 0; j < 4; ++j) acc4[j] = make_float4(0.f, 0.f, 0.f, 0.f);
            for (int d = 0; d < DIM; ++d) {
                float xd = xr[d];
                #pragma unroll
                for (int j = 0; j < 4; ++j) {
                    float4 ev = *reinterpret_cast<const float4*>(
                        E + (size_t)d * KCODES + j * 128 + lane * 4);
                    acc4[j].x = fmaf(xd, ev.x, acc4[j].x);
                    acc4[j].y = fmaf(xd, ev.y, acc4[j].y);
                    acc4[j].z = fmaf(xd, ev.z, acc4[j].z);
                    acc4[j].w = fmaf(xd, ev.w, acc4[j].w);
                }
            }
            float bv = CUDART_INF_F;
            int   bi = 0;
            #pragma unroll
            for (int j = 0; j < 4; ++j) {
                float dv[4] = {acc4[j].x, acc4[j].y, acc4[j].z, acc4[j].w};
                #pragma unroll
                for (int e = 0; e < 4; ++e) {
                    int   c = j * 128 + lane * 4 + e;
                    float v = fmaf(-2.f, dv[e], enorm_s[c]);
                    if (v < bv) { bv = v; bi = c; }
                }
            }
            #pragma unroll
            for (int st = 16; st > 0; st >>= 1) {
                float ov = __shfl_xor_sync(0xffffffffu, bv, st);
                int   oi = __shfl_xor_sync(0xffffffffu, bi, st);
                if (ov < bv || (ov == bv && oi < bi)) { bv = ov; bi = oi; }
            }
            if (lane == 0) {
                rowcode[r] = bi;
                size_t p = IDX_OFF + (size_t)(rowBase + r);
                if (p < (size_t)out_size) out[p] = (float)bi;
            }
        }
    }
    __syncthreads();

    // ---- gather quantized via transposed ET (coalesced), loss ----
    float lsum = 0.f;
    #pragma unroll 4
    for (int i = tid; i < ROWS_BLK * DIM; i += THREADS) {
        int r = i >> 6, d = i & 63;
        int code = rowcode[r];
        float qv = g_ET[code * DIM + d];
        float xv = X[(size_t)(rowBase + r) * DIM + d];
        out[(size_t)(rowBase + r) * DIM + d] = qv;
        float df = qv - xv;
        lsum = fmaf(df, df, lsum);
    }

    // ---- block loss reduction ----
    __syncthreads();
    float* red = reinterpret_cast<float*>(smem + OFF_A);   // A dead now
    red[tid] = lsum;
    __syncthreads();
    #pragma unroll
    for (int s = THREADS / 2; s > 0; s >>= 1) {
        if (tid < s) red[tid] += red[tid + s];
        __syncthreads();
    }

    // ---- last-block deterministic final loss reduction ----
    __shared__ int islast;
    if (tid == 0) {
        g_partials[blockIdx.x] = red[0];
        __threadfence();
        int tk = atomicAdd(&g_done, 1);
        islast = (tk == NCTAS - 1) ? 1 : 0;
    }
    __syncthreads();
    if (islast) {
        volatile float* gp = g_partials;
        float s = (tid < NCTAS) ? gp[tid] : 0.f;
        red[tid] = s;
        __syncthreads();
        #pragma unroll
        for (int st = THREADS / 2; st > 0; st >>= 1) {
            if (tid < st) red[tid] += red[tid + st];
            __syncthreads();
        }
        if (tid == 0) {
            float loss = 1.25f * red[0] / (float)Q_ELEMS;
            if (LOSS_OFF < (size_t)out_size) out[LOSS_OFF] = loss;
            g_done = 0;                     // reset for next graph replay
        }
    }
}

// ---------------------------------------------------------------------------
extern "C" void kernel_launch(void* const* d_in, const int* in_sizes, int n_in,
                              void* d_out, int out_size) {
    const float* X;
    const float* E;
    if (in_sizes[0] == DIM * KCODES && in_sizes[1] != DIM * KCODES) {
        E = (const float*)d_in[0];
        X = (const float*)d_in[1];
    } else {
        X = (const float*)d_in[0];
        E = (const float*)d_in[1];
    }
    float* out = (float*)d_out;

    static bool attr_done = false;
    if (!attr_done) {
        cudaFuncSetAttribute(vq_kernel,
                             cudaFuncAttributeMaxDynamicSharedMemorySize, SMEM_TOTAL);
        attr_done = true;
    }

    vq_prep_kernel<<<64, 512>>>(E);
    vq_kernel<<<NCTAS, THREADS, SMEM_TOTAL>>>(X, E, out, out_size);
}

// round 12
// speedup vs baseline: 1.2920x; 1.0424x over previous
#include <cuda_runtime.h>
#include <cuda_fp16.h>
#include <math_constants.h>

typedef unsigned int u32;

// Problem: inputs [64,32,32,64] f32 -> N=65536 rows, D=64; embeddings [64,512] f32.
// Output (f32 concat): quantized [N*64] | indices [N] | loss [1]
#define N_ROWS   65536
#define DIM      64
#define KCODES   512
#define ROWS_BLK 256
#define THREADS  512
#define NCTAS    (N_ROWS / ROWS_BLK)     // 256 CTAs, single wave

#define Q_ELEMS  ((size_t)N_ROWS * DIM)
#define IDX_OFF  Q_ELEMS
#define LOSS_OFF (Q_ELEMS + N_ROWS)

// SMEM layout (bytes)
#define ASTRIDE   144                    // A: 128B fp16 row + 16B pad
#define BSTRIDE   144                    // B: [code][d] 128B row + 16B pad
#define OFF_A     0                                   // 256*144 = 36864
#define OFF_B     (OFF_A + ROWS_BLK * ASTRIDE)        // 36864
#define OFF_ENORM (OFF_B + KCODES * BSTRIDE)          // 36864+73728 = 110592
#define SMEM_TOTAL (OFF_ENORM + KCODES * 4)           // 112640 -> 2 CTAs/SM
// post-mainloop overlays inside dead A region:
#define OFF_FLAGC   0
#define OFF_FLAGL   16
#define OFF_ROWCODE 2048
#define OFF_RED     4096

// fp16 flip band ~0.032 + packing error <0.001 -> 0.09 is ample.
#define BAND_T 0.09f

__device__ float  g_partials[NCTAS];
__device__ int    g_done = 0;
__device__ __half g_B2h[KCODES * DIM];   // fp16 (-2*E), [code][d]
__device__ float  g_ET[KCODES * DIM];    // fp32 E transposed, [code][d]
__device__ float  g_enorm[KCODES];

// ---------------------------------------------------------------------------
static __device__ __forceinline__ u32 smem_u32(const void* p) {
    u32 a;
    asm("{ .reg .u64 t; cvta.to.shared.u64 t, %1; cvt.u32.u64 %0, t; }" : "=r"(a) : "l"(p));
    return a;
}
static __device__ __forceinline__ void ldsm_x4(u32& r0, u32& r1, u32& r2, u32& r3, u32 a) {
    asm volatile("ldmatrix.sync.aligned.m8n8.x4.shared.b16 {%0,%1,%2,%3}, [%4];"
                 : "=r"(r0), "=r"(r1), "=r"(r2), "=r"(r3) : "r"(a));
}
static __device__ __forceinline__ void mma_f16(float* c, const u32* a, u32 b0, u32 b1) {
    asm volatile("mma.sync.aligned.m16n8k16.row.col.f32.f16.f16.f32 "
                 "{%0,%1,%2,%3}, {%4,%5,%6,%7}, {%8,%9}, {%0,%1,%2,%3};"
                 : "+f"(c[0]), "+f"(c[1]), "+f"(c[2]), "+f"(c[3])
                 : "r"(a[0]), "r"(a[1]), "r"(a[2]), "r"(a[3]), "r"(b0), "r"(b1));
}
// first k-step: C operand = {enorm0, enorm1, enorm0, enorm1} (distance init for free)
static __device__ __forceinline__ void mma_f16_init(float* d, const u32* a, u32 b0, u32 b1,
                                                    float e0, float e1) {
    asm volatile("mma.sync.aligned.m16n8k16.row.col.f32.f16.f16.f32 "
                 "{%0,%1,%2,%3}, {%4,%5,%6,%7}, {%8,%9}, {%10,%11,%10,%11};"
                 : "=f"(d[0]), "=f"(d[1]), "=f"(d[2]), "=f"(d[3])
                 : "r"(a[0]), "r"(a[1]), "r"(a[2]), "r"(a[3]), "r"(b0), "r"(b1),
                   "f"(e0), "f"(e1));
}
// pack code into low 9 mantissa bits of distance (|dist|<16 -> error < 1e-3)
static __device__ __forceinline__ float packkey(float v, int code) {
    return __uint_as_float((__float_as_uint(v) & 0xFFFFFE00u) | (u32)code);
}

// ---------------------------------------------------------------------------
// Kernel 1: prep — fp16 (-2E) [code][d], fp32 E^T, enorm
// ---------------------------------------------------------------------------
__global__ void vq_prep_kernel(const float* __restrict__ E) {
    int gid = blockIdx.x * 512 + threadIdx.x;        // 0..32767 == d*512 + code
    float v = E[gid];
    int d = gid >> 9, c = gid & 511;
    g_B2h[c * DIM + d] = __float2half_rn(-2.f * v);
    g_ET[c * DIM + d]  = v;
    if (gid < KCODES) {
        float s = 0.f;
        #pragma unroll 16
        for (int dd = 0; dd < DIM; ++dd) {
            float e = E[(size_t)dd * KCODES + gid];
            s = fmaf(e, e, s);
        }
        g_enorm[gid] = s;
    }
}

// ---------------------------------------------------------------------------
// Kernel 2: main — non-trans B fragments, enorm folded into MMA C-init
// ---------------------------------------------------------------------------
__global__ void __launch_bounds__(THREADS, 2)
vq_kernel(const float* __restrict__ X, const float* __restrict__ E,
          float* __restrict__ out, int out_size) {
    extern __shared__ char smem[];
    const u32 sb   = smem_u32(smem);
    const int tid  = threadIdx.x;
    const int lane = tid & 31;
    const int warp = tid >> 5;                // 0..15
    const int rowBase = blockIdx.x * ROWS_BLK;
    const int warpRow = warp * 16;

    float* enorm_s  = reinterpret_cast<float*>(smem + OFF_ENORM);
    int*   rowcode  = reinterpret_cast<int*>(smem + OFF_ROWCODE);
    int*   flagcnt  = reinterpret_cast<int*>(smem + OFF_FLAGC);
    int*   flaglist = reinterpret_cast<int*>(smem + OFF_FLAGL);

    // ---- A tile: fp32 -> fp16, [row][d] stride 144 ----
    #pragma unroll
    for (int it = 0; it < 4; ++it) {
        int task = tid + THREADS * it;        // 2048 tasks: 256 rows x 8 groups
        int r  = task >> 3;
        int d0 = (task & 7) * 8;
        const float4* xv = reinterpret_cast<const float4*>(
            X + (size_t)(rowBase + r) * DIM + d0);
        float4 v0 = xv[0], v1 = xv[1];
        float vals[8] = {v0.x, v0.y, v0.z, v0.w, v1.x, v1.y, v1.z, v1.w};
        union { __half h[8]; uint4 u; } ph;
        #pragma unroll
        for (int e = 0; e < 8; ++e) ph.h[e] = __float2half_rn(vals[e]);
        *reinterpret_cast<uint4*>(smem + OFF_A + r * ASTRIDE + d0 * 2) = ph.u;
    }
    // ---- B: copy -2E fp16 [code][d] rows (stride 144) ----
    {
        const uint4* src = reinterpret_cast<const uint4*>(g_B2h);
        #pragma unroll
        for (int it = 0; it < 8; ++it) {
            int i = tid + THREADS * it;       // 4096 uint4: 512 codes x 8 groups
            int c = i >> 3, q = i & 7;
            *reinterpret_cast<uint4*>(smem + OFF_B + c * BSTRIDE + q * 16) = src[i];
        }
    }
    enorm_s[tid] = g_enorm[tid];
    __syncthreads();

    // ---- hoisted A fragments ----
    const int mA = lane >> 3, rA8 = lane & 7;
    const u32 aBase = sb + OFF_A + (u32)((warpRow + (mA & 1) * 8 + rA8) * ASTRIDE
                                         + (mA >> 1) * 16);
    u32 af[4][4];
    #pragma unroll
    for (int ks = 0; ks < 4; ++ks)
        ldsm_x4(af[ks][0], af[ks][1], af[ks][2], af[ks][3], aBase + ks * 32);

    // B non-trans ldsm base: tiles = (codes 0-7 | +8) x (k-lo | k-hi)
    const u32 bBase = sb + OFF_B
        + (u32)(((lane & 7) + ((lane >> 4) & 1) * 8) * BSTRIDE + ((lane >> 3) & 1) * 16);
    const int colBase = 2 * (lane & 3);

    // packed top-2 keys per row pair
    float k1a = CUDART_INF_F, k2a = CUDART_INF_F;
    float k1b = CUDART_INF_F, k2b = CUDART_INF_F;

    // ---- mainloop: 16 subchunks of 32 codes, barrier-free ----
    #pragma unroll 1
    for (int s = 0; s < 16; ++s) {
        const int c0 = s * 32;
        const u32 bRow = bBase + (u32)(c0 * BSTRIDE);

        u32 p[4], q[4];
        ldsm_x4(p[0], p[1], p[2], p[3], bRow);                      // codes c0..c0+15
        ldsm_x4(q[0], q[1], q[2], q[3], bRow + 16 * BSTRIDE);       // codes c0+16..+31

        float2 e0 = *reinterpret_cast<const float2*>(&enorm_s[c0 +  0 + colBase]);
        float2 e1 = *reinterpret_cast<const float2*>(&enorm_s[c0 +  8 + colBase]);
        float2 e2 = *reinterpret_cast<const float2*>(&enorm_s[c0 + 16 + colBase]);
        float2 e3 = *reinterpret_cast<const float2*>(&enorm_s[c0 + 24 + colBase]);

        float acc[4][4];
        mma_f16_init(acc[0], af[0], p[0], p[1], e0.x, e0.y);
        mma_f16_init(acc[1], af[0], p[2], p[3], e1.x, e1.y);
        mma_f16_init(acc[2], af[0], q[0], q[1], e2.x, e2.y);
        mma_f16_init(acc[3], af[0], q[2], q[3], e3.x, e3.y);

        #pragma unroll
        for (int ks = 1; ks < 4; ++ks) {
            ldsm_x4(p[0], p[1], p[2], p[3], bRow + ks * 32);
            ldsm_x4(q[0], q[1], q[2], q[3], bRow + 16 * BSTRIDE + ks * 32);
            mma_f16(acc[0], af[ks], p[0], p[1]);
            mma_f16(acc[1], af[ks], p[2], p[3]);
            mma_f16(acc[2], af[ks], q[0], q[1]);
            mma_f16(acc[3], af[ks], q[2], q[3]);
        }

        // acc IS the distance now: pack + top-2 (3 ops per value)
        #pragma unroll
        for (int nt = 0; nt < 4; ++nt) {
            int code0 = c0 + nt * 8 + colBase;
            float pk;
            #define UPD(K1, K2, VAL, IDX)                            \
                do { pk = packkey((VAL), (IDX));                     \
                     K2 = fminf(K2, fmaxf(K1, pk));                  \
                     K1 = fminf(K1, pk); } while (0)
            UPD(k1a, k2a, acc[nt][0], code0);
            UPD(k1a, k2a, acc[nt][1], code0 + 1);
            UPD(k1b, k2b, acc[nt][2], code0);
            UPD(k1b, k2b, acc[nt][3], code0 + 1);
            #undef UPD
        }
    }

    // A region is dead now (fragments in registers): init flag overlay safely
    __syncthreads();
    if (tid == 0) *flagcnt = 0;
    __syncthreads();

    // ---- cross-lane top-2 merge within quad (pure float min/max) ----
    #define MERGE(K1, K2, OFFX)                                              \
        do {                                                                 \
            float o1 = __shfl_xor_sync(0xffffffffu, K1, OFFX);               \
            float o2 = __shfl_xor_sync(0xffffffffu, K2, OFFX);               \
            K2 = fminf(fminf(K2, o2), fmaxf(K1, o1));                        \
            K1 = fminf(K1, o1);                                              \
        } while (0)
    MERGE(k1a, k2a, 1);
    MERGE(k1a, k2a, 2);
    MERGE(k1b, k2b, 1);
    MERGE(k1b, k2b, 2);
    #undef MERGE

    if ((lane & 3) == 0) {
        int q  = lane >> 2;
        int rA = warpRow + q;
        int rB = warpRow + q + 8;
        int i1a = (int)(__float_as_uint(k1a) & 511u);
        int i1b = (int)(__float_as_uint(k1b) & 511u);
        rowcode[rA] = i1a;
        rowcode[rB] = i1b;
        size_t pA = IDX_OFF + (size_t)(rowBase + rA);
        size_t pB = IDX_OFF + (size_t)(rowBase + rB);
        if (pA < (size_t)out_size) out[pA] = (float)i1a;
        if (pB < (size_t)out_size) out[pB] = (float)i1b;
        if (k2a - k1a < BAND_T) flaglist[atomicAdd(flagcnt, 1)] = rA;
        if (k2b - k1b < BAND_T) flaglist[atomicAdd(flagcnt, 1)] = rB;
    }
    __syncthreads();

    // ---- exact fp32 full rescan of flagged rows, one warp per row ----
    {
        int nflag = *flagcnt;
        for (int f = warp; f < nflag; f += 16) {
            int r = flaglist[f];
            const float* xr = X + (size_t)(rowBase + r) * DIM;
            float4 acc4[4];
            #pragma unroll
            for (int j = 0; j < 4; ++j) acc4[j] = make_float4(0.f, 0.f, 0.f, 0.f);
            for (int d = 0; d < DIM; ++d) {
                float xd = xr[d];
                #pragma unroll
                for (int j = 0; j < 4; ++j) {
                    float4 ev = *reinterpret_cast<const float4*>(
                        E + (size_t)d * KCODES + j * 128 + lane * 4);
                    acc4[j].x = fmaf(xd, ev.x, acc4[j].x);
                    acc4[j].y = fmaf(xd, ev.y, acc4[j].y);
                    acc4[j].z = fmaf(xd, ev.z, acc4[j].z);
                    acc4[j].w = fmaf(xd, ev.w, acc4[j].w);
                }
            }
            float bv = CUDART_INF_F;
            int   bi = 0;
            #pragma unroll
            for (int j = 0; j < 4; ++j) {
                float dv[4] = {acc4[j].x, acc4[j].y, acc4[j].z, acc4[j].w};
                #pragma unroll
                for (int e = 0; e < 4; ++e) {
                    int   c = j * 128 + lane * 4 + e;
                    float v = fmaf(-2.f, dv[e], enorm_s[c]);
                    if (v < bv) { bv = v; bi = c; }
                }
            }
            #pragma unroll
            for (int st = 16; st > 0; st >>= 1) {
                float ov = __shfl_xor_sync(0xffffffffu, bv, st);
                int   oi = __shfl_xor_sync(0xffffffffu, bi, st);
                if (ov < bv || (ov == bv && oi < bi)) { bv = ov; bi = oi; }
            }
            if (lane == 0) {
                rowcode[r] = bi;
                size_t p = IDX_OFF + (size_t)(rowBase + r);
                if (p < (size_t)out_size) out[p] = (float)bi;
            }
        }
    }
    __syncthreads();

    // ---- gather quantized via transposed ET (coalesced), loss ----
    float lsum = 0.f;
    #pragma unroll 4
    for (int i = tid; i < ROWS_BLK * DIM; i += THREADS) {
        int r = i >> 6, d = i & 63;
        int code = rowcode[r];
        float qv = g_ET[code * DIM + d];
        float xv = X[(size_t)(rowBase + r) * DIM + d];
        out[(size_t)(rowBase + r) * DIM + d] = qv;
        float df = qv - xv;
        lsum = fmaf(df, df, lsum);
    }

    // ---- block loss reduction ----
    __syncthreads();
    float* red = reinterpret_cast<float*>(smem + OFF_RED);
    red[tid] = lsum;
    __syncthreads();
    #pragma unroll
    for (int s = THREADS / 2; s > 0; s >>= 1) {
        if (tid < s) red[tid] += red[tid + s];
        __syncthreads();
    }

    // ---- last-block deterministic final loss reduction ----
    __shared__ int islast;
    if (tid == 0) {
        g_partials[blockIdx.x] = red[0];
        __threadfence();
        int tk = atomicAdd(&g_done, 1);
        islast = (tk == NCTAS - 1) ? 1 : 0;
    }
    __syncthreads();
    if (islast) {
        volatile float* gp = g_partials;
        float s = (tid < NCTAS) ? gp[tid] : 0.f;
        red[tid] = s;
        __syncthreads();
        #pragma unroll
        for (int st = THREADS / 2; st > 0; st >>= 1) {
            if (tid < st) red[tid] += red[tid + st];
            __syncthreads();
        }
        if (tid == 0) {
            float loss = 1.25f * red[0] / (float)Q_ELEMS;
            if (LOSS_OFF < (size_t)out_size) out[LOSS_OFF] = loss;
            g_done = 0;                     // reset for next graph replay
        }
    }
}

// ---------------------------------------------------------------------------
extern "C" void kernel_launch(void* const* d_in, const int* in_sizes, int n_in,
                              void* d_out, int out_size) {
    const float* X;
    const float* E;
    if (in_sizes[0] == DIM * KCODES && in_sizes[1] != DIM * KCODES) {
        E = (const float*)d_in[0];
        X = (const float*)d_in[1];
    } else {
        X = (const float*)d_in[0];
        E = (const float*)d_in[1];
    }
    float* out = (float*)d_out;

    static bool attr_done = false;
    if (!attr_done) {
        cudaFuncSetAttribute(vq_kernel,
                             cudaFuncAttributeMaxDynamicSharedMemorySize, SMEM_TOTAL);
        attr_done = true;
    }

    vq_prep_kernel<<<64, 512>>>(E);
    vq_kernel<<<NCTAS, THREADS, SMEM_TOTAL>>>(X, E, out, out_size);
}